// round 12
// baseline (speedup 1.0000x reference)
#include <cuda_runtime.h>
#include <cuda_fp16.h>
#include <math.h>
#include <stdint.h>

#define TTOK 4096
#define HDIM 2048
#define NEXP 64
#define TOPK 8
#define IDIM 768
#define NPAIR (TTOK * TOPK)
#define CAP   TTOK

/* ---------------- scratch ---------------- */
__device__ float g_logits[TTOK * NEXP];
__device__ float g_topkw[NPAIR];
__device__ int   g_counts[NEXP];
__device__ int   g_offsets[NEXP];
__device__ int   g_bucket[NEXP * CAP];
__device__ uint4 g_act4[(size_t)NPAIR * IDIM / 8];          /* fp16 silu(g)*u     */
__device__ uint4 g_gb[(size_t)NPAIR * IDIM / 8];            /* fp16 gate result   */
__device__ uint4 g_ub[(size_t)NPAIR * IDIM / 8];            /* fp16 up result     */
__device__ uint4 g_xh[(size_t)TTOK * HDIM / 8];             /* fp16 tokens        */
__device__ uint4 g_wgh[(size_t)NEXP * HDIM * IDIM / 8];     /* fp16 w_gate        */
__device__ uint4 g_wuh[(size_t)NEXP * HDIM * IDIM / 8];     /* fp16 w_up          */
__device__ uint4 g_wdh[(size_t)NEXP * IDIM * HDIM / 8];     /* fp16 w_down        */

#define LD4(p) (*reinterpret_cast<const float4*>(p))

/* ---------------- helpers ---------------- */
__device__ __forceinline__ uint32_t smem_u32(const void* p) {
    uint32_t a;
    asm("{ .reg .u64 t; cvta.to.shared.u64 t, %1; cvt.u32.u64 %0, t; }" : "=r"(a) : "l"(p));
    return a;
}
__device__ __forceinline__ uint32_t pk2(float x, float y) {
    __half2 h = __floats2half2_rn(x, y);
    return *reinterpret_cast<uint32_t*>(&h);
}
__device__ __forceinline__ void ldsm4(uint32_t* r, uint32_t addr) {
    asm volatile("ldmatrix.sync.aligned.m8n8.x4.shared.b16 {%0,%1,%2,%3}, [%4];"
                 : "=r"(r[0]), "=r"(r[1]), "=r"(r[2]), "=r"(r[3]) : "r"(addr));
}
__device__ __forceinline__ void ldsm4t(uint32_t* r, uint32_t addr) {
    asm volatile("ldmatrix.sync.aligned.m8n8.x4.trans.shared.b16 {%0,%1,%2,%3}, [%4];"
                 : "=r"(r[0]), "=r"(r[1]), "=r"(r[2]), "=r"(r[3]) : "r"(addr));
}
__device__ __forceinline__ void mma16(float* d, const uint32_t* a, const uint32_t* b) {
    asm volatile(
        "mma.sync.aligned.m16n8k16.row.col.f32.f16.f16.f32 "
        "{%0,%1,%2,%3}, {%4,%5,%6,%7}, {%8,%9}, {%0,%1,%2,%3};"
        : "+f"(d[0]), "+f"(d[1]), "+f"(d[2]), "+f"(d[3])
        : "r"(a[0]), "r"(a[1]), "r"(a[2]), "r"(a[3]), "r"(b[0]), "r"(b[1]));
}
__device__ __forceinline__ void cpa16(uint32_t sdst, const void* gsrc, uint32_t sz) {
    asm volatile("cp.async.cg.shared.global [%0], [%1], 16, %2;"
                 :: "r"(sdst), "l"(gsrc), "r"(sz) : "memory");
}
__device__ __forceinline__ void cpa_commit() {
    asm volatile("cp.async.commit_group;" ::: "memory");
}
__device__ __forceinline__ void cpa_wait1() {
    asm volatile("cp.async.wait_group 1;" ::: "memory");
}

/* sub-chunk (16-k): A[128][24] (48B rows), B[16][136] (272B rows).
   One pipeline stage = TWO consecutive sub-chunks (BK=32). */
#define A_LDA 24
#define B_LDB 136
#define A_HALVES (128 * A_LDA)
#define B_HALVES (16 * B_LDB)
#define G_SUB_H (A_HALVES + B_HALVES)            /* 5248 halves */
#define G_STAGE_H (2 * G_SUB_H)                  /* 10496 halves */
#define G_SMEM (512 + 3 * G_STAGE_H * 2)         /* ~63KB -> 2 CTAs/SM */

/* ---------------- small kernels ---------------- */
__global__ void k_zero_counts() { if (threadIdx.x < NEXP) g_counts[threadIdx.x] = 0; }

__global__ void k_zero_out(float4* __restrict__ out) {
    size_t i = (size_t)blockIdx.x * blockDim.x + threadIdx.x;
    if (i < (size_t)TTOK * HDIM / 4) out[i] = make_float4(0.f, 0.f, 0.f, 0.f);
}

/* fp32 -> fp16 bulk convert. dst selected DEVICE-SIDE (host shadow-symbol trap). */
__global__ void __launch_bounds__(256) k_cvt(const float4* __restrict__ src,
                                             int which, size_t n8) {
    size_t i = (size_t)blockIdx.x * blockDim.x + threadIdx.x;
    if (i >= n8) return;
    uint4* dst = (which == 0) ? g_wgh : (which == 1) ? g_wuh : (which == 2) ? g_wdh : g_xh;
    float4 a = src[2 * i], b = src[2 * i + 1];
    dst[i] = make_uint4(pk2(a.x, a.y), pk2(a.z, a.w), pk2(b.x, b.y), pk2(b.z, b.w));
}

/* elementwise act = silu(g) * u, fp16 in/out, 8 elems/thread */
__global__ void __launch_bounds__(256) k_silu() {
    size_t i = (size_t)blockIdx.x * blockDim.x + threadIdx.x;
    if (i >= (size_t)NPAIR * IDIM / 8) return;
    uint4 gv = g_gb[i], uv = g_ub[i];
    const uint32_t* gw = &gv.x;
    const uint32_t* uw = &uv.x;
    uint4 o;
    uint32_t* ow = &o.x;
#pragma unroll
    for (int j = 0; j < 4; j++) {
        __half2 gh = *reinterpret_cast<const __half2*>(&gw[j]);
        __half2 uh = *reinterpret_cast<const __half2*>(&uw[j]);
        float2 gf = __half22float2(gh), uf = __half22float2(uh);
        float o0 = gf.x / (1.f + expf(-gf.x)) * uf.x;
        float o1 = gf.y / (1.f + expf(-gf.y)) * uf.y;
        ow[j] = pk2(o0, o1);
    }
    g_act4[i] = o;
}

__global__ void __launch_bounds__(256) k_router(const float* __restrict__ x,
                                                const float* __restrict__ gw) {
    __shared__ float As[16][64];
    __shared__ float Bs[16][64];
    const int t = threadIdx.x;
    const int m0 = blockIdx.x * 64;
    const int tx = t & 15, ty = t >> 4;
    const int mload = t >> 2;
    const int kq = (t & 3) * 4;
    float acc[4][4] = {};
    for (int k0 = 0; k0 < HDIM; k0 += 16) {
        float4 av = LD4(x + (size_t)(m0 + mload) * HDIM + k0 + kq);
        float4 bv = LD4(gw + (size_t)mload * HDIM + k0 + kq);
        __syncthreads();
        As[kq + 0][mload] = av.x; As[kq + 1][mload] = av.y;
        As[kq + 2][mload] = av.z; As[kq + 3][mload] = av.w;
        Bs[kq + 0][mload] = bv.x; Bs[kq + 1][mload] = bv.y;
        Bs[kq + 2][mload] = bv.z; Bs[kq + 3][mload] = bv.w;
        __syncthreads();
#pragma unroll
        for (int k = 0; k < 16; k++) {
            float4 a = LD4(&As[k][ty * 4]);
            float4 b = LD4(&Bs[k][tx * 4]);
            float ax[4] = {a.x, a.y, a.z, a.w};
            float bx[4] = {b.x, b.y, b.z, b.w};
#pragma unroll
            for (int i = 0; i < 4; i++)
#pragma unroll
                for (int j = 0; j < 4; j++)
                    acc[i][j] = fmaf(ax[i], bx[j], acc[i][j]);
        }
    }
#pragma unroll
    for (int i = 0; i < 4; i++)
#pragma unroll
        for (int j = 0; j < 4; j++)
            g_logits[(size_t)(m0 + ty * 4 + i) * NEXP + tx * 4 + j] = acc[i][j];
}

__global__ void k_topk() {
    int t = blockIdx.x * blockDim.x + threadIdx.x;
    if (t >= TTOK) return;
    float l[NEXP];
    for (int e = 0; e < NEXP; e++) l[e] = g_logits[(size_t)t * NEXP + e];
    float vals[TOPK]; int ids[TOPK];
    for (int k = 0; k < TOPK; k++) {
        float best = -3.4e38f; int bi = 0;
        for (int e = 0; e < NEXP; e++)
            if (l[e] > best) { best = l[e]; bi = e; }
        vals[k] = best; ids[k] = bi; l[bi] = -3.4e38f;
    }
    float m = vals[0], s = 0.f, wv[TOPK];
    for (int k = 0; k < TOPK; k++) { wv[k] = expf(vals[k] - m); s += wv[k]; }
    float inv = 1.f / s;
    for (int k = 0; k < TOPK; k++) {
        g_topkw[t * TOPK + k] = wv[k] * inv;
        int e = ids[k];
        int pos = atomicAdd(&g_counts[e], 1);
        g_bucket[e * CAP + pos] = t * TOPK + k;
    }
}

__global__ void k_scan() {
    int s = 0;
    for (int e = 0; e < NEXP; e++) { g_offsets[e] = s; s += g_counts[e]; }
}

/* ======= stage 4: gate OR up fp16 HMMA, BK=32 stages, 2 CTAs/SM ===== */
__global__ void __launch_bounds__(256, 2)
k_gemm1() {
    extern __shared__ char smraw[];
    const int e = blockIdx.z >> 1;
    const int which = blockIdx.z & 1;
    const int rows = g_counts[e];
    const int m0 = blockIdx.y * 128;
    if (m0 >= rows) return;
    const int n0 = blockIdx.x * 128;
    const int t = threadIdx.x, w = t >> 5, lane = t & 31;
    const int gid = lane >> 2, tig = lane & 3;
    const int wm = w >> 2, wn = w & 3;

    int* toks = (int*)smraw;
    __half* buf = (__half*)(smraw + 512);
    if (t < 128) {
        int r = m0 + t;
        toks[t] = (r < rows) ? (g_bucket[e * CAP + r] >> 3) : -1;
    }
    __syncthreads();

    const __half* xh = (const __half*)g_xh;
    const __half* wh = (const __half*)(which ? g_wuh : g_wgh) + (size_t)e * HDIM * IDIM;

    const int am = t >> 1, ah = (t & 1) * 8;
    const int tokA = toks[am];
    const uint32_t asz = (tokA >= 0) ? 16u : 0u;
    const __half* aptr = xh + (size_t)(tokA >= 0 ? tokA : 0) * HDIM;
    const int bk = t >> 4, bn = (t & 15) * 8;
    const __half* bptr = wh + (size_t)bk * IDIM + n0 + bn;

    const uint32_t sb = smem_u32(buf);
    const uint32_t aDst = sb + (uint32_t)(am * A_LDA + ah) * 2;
    const uint32_t bDst = sb + (uint32_t)(A_HALVES + bk * B_LDB + bn) * 2;

    const int KT = HDIM / 32;    /* 64 BK=32 stages */
#define G1_ISSUE(s) { \
        const uint32_t so = (uint32_t)((s) % 3) * (G_STAGE_H * 2); \
        _Pragma("unroll") \
        for (int c = 0; c < 2; c++) { \
            const int kb = (s) * 32 + c * 16; \
            const uint32_t co = so + (uint32_t)c * (G_SUB_H * 2); \
            cpa16(aDst + co, aptr + kb + ah, asz); \
            cpa16(bDst + co, bptr + (size_t)kb * IDIM, 16u); \
        } \
    }
    G1_ISSUE(0); cpa_commit();
    G1_ISSUE(1); cpa_commit();

    float cg[4][4][4] = {};
    const int aRow = wm * 64 + (lane & 15);
    const int aK   = (lane >> 4) * 8;
    const int bRow = lane & 15;
    const int bOct = (lane >> 4) * 8;

    for (int kt = 0; kt < KT; kt++) {
        cpa_wait1();
        __syncthreads();
        if (kt + 2 < KT) G1_ISSUE(kt + 2);
        cpa_commit();
        __half* stage = buf + (kt % 3) * G_STAGE_H;
#pragma unroll
        for (int c = 0; c < 2; c++) {
            __half* stc = stage + c * G_SUB_H;
            const uint32_t aAddr = smem_u32(stc + aRow * A_LDA + aK);
            const uint32_t bAddr = smem_u32(stc + A_HALVES + bRow * B_LDB + wn * 32 + bOct);
            uint32_t af[4][4], bg[2][4];
#pragma unroll
            for (int mt = 0; mt < 4; mt++) ldsm4(af[mt], aAddr + mt * 16 * A_LDA * 2);
#pragma unroll
            for (int p = 0; p < 2; p++) ldsm4t(bg[p], bAddr + p * 32);
#pragma unroll
            for (int nt = 0; nt < 4; nt++) {
                const uint32_t* b = &bg[nt >> 1][(nt & 1) * 2];
#pragma unroll
                for (int mt = 0; mt < 4; mt++) mma16(cg[mt][nt], af[mt], b);
            }
        }
    }
#undef G1_ISSUE
    /* epilogue -> raw fp16 gate/up buffer */
    __half* gout = (__half*)(which ? g_ub : g_gb);
    const int off = g_offsets[e];
#pragma unroll
    for (int mt = 0; mt < 4; mt++) {
#pragma unroll
        for (int h = 0; h < 2; h++) {
            const int row = m0 + wm * 64 + mt * 16 + gid + h * 8;
            if (row < rows) {
                __half* dst = gout + (size_t)(off + row) * IDIM + n0 + wn * 32;
#pragma unroll
                for (int nt = 0; nt < 4; nt++)
                    *reinterpret_cast<uint32_t*>(dst + nt * 8 + 2 * tig) =
                        pk2(cg[mt][nt][h * 2 + 0], cg[mt][nt][h * 2 + 1]);
            }
        }
    }
}

/* ===== stage 5: down-proj fp16 HMMA + fused combine, BK=32 stages ===== */
__global__ void __launch_bounds__(256, 2)
k_gemm2(float* __restrict__ out) {
    extern __shared__ char smraw[];
    const int e = blockIdx.z;
    const int rows = g_counts[e];
    const int m0 = blockIdx.y * 128;
    if (m0 >= rows) return;
    const int n0 = blockIdx.x * 128;
    const int t = threadIdx.x, w = t >> 5, lane = t & 31;
    const int gid = lane >> 2, tig = lane & 3;
    const int wm = w >> 2, wn = w & 3;
    const int off = g_offsets[e];

    int* prs = (int*)smraw;
    __half* buf = (__half*)(smraw + 512);
    if (t < 128) {
        int r = m0 + t;
        prs[t] = (r < rows) ? g_bucket[e * CAP + r] : -1;
    }
    __syncthreads();

    const __half* gact = (const __half*)g_act4;
    const __half* wdh  = (const __half*)g_wdh + (size_t)e * IDIM * HDIM;

    const int am = t >> 1, ah = (t & 1) * 8;
    const uint32_t asz = (m0 + am < rows) ? 16u : 0u;
    const __half* aptr = gact + (size_t)(off + m0 + ((m0 + am < rows) ? am : 0)) * IDIM;
    const int bk = t >> 4, bn = (t & 15) * 8;
    const __half* bptr = wdh + (size_t)bk * HDIM + n0 + bn;

    const uint32_t sb = smem_u32(buf);
    const uint32_t aDst = sb + (uint32_t)(am * A_LDA + ah) * 2;
    const uint32_t bDst = sb + (uint32_t)(A_HALVES + bk * B_LDB + bn) * 2;

    const int KT = IDIM / 32;    /* 24 BK=32 stages */
#define G2_ISSUE(s) { \
        const uint32_t so = (uint32_t)((s) % 3) * (G_STAGE_H * 2); \
        _Pragma("unroll") \
        for (int c = 0; c < 2; c++) { \
            const int kb = (s) * 32 + c * 16; \
            const uint32_t co = so + (uint32_t)c * (G_SUB_H * 2); \
            cpa16(aDst + co, aptr + kb + ah, asz); \
            cpa16(bDst + co, bptr + (size_t)kb * HDIM, 16u); \
        } \
    }
    G2_ISSUE(0); cpa_commit();
    G2_ISSUE(1); cpa_commit();

    float cd[4][4][4] = {};
    const int aRow = wm * 64 + (lane & 15);
    const int aK   = (lane >> 4) * 8;
    const int bRow = lane & 15;
    const int bOct = (lane >> 4) * 8;

    for (int kt = 0; kt < KT; kt++) {
        cpa_wait1();
        __syncthreads();
        if (kt + 2 < KT) G2_ISSUE(kt + 2);
        cpa_commit();
        __half* stage = buf + (kt % 3) * G_STAGE_H;
#pragma unroll
        for (int c = 0; c < 2; c++) {
            __half* stc = stage + c * G_SUB_H;
            const uint32_t aAddr = smem_u32(stc + aRow * A_LDA + aK);
            const uint32_t bAddr = smem_u32(stc + A_HALVES + bRow * B_LDB + wn * 32 + bOct);
            uint32_t af[4][4], bd[2][4];
#pragma unroll
            for (int mt = 0; mt < 4; mt++) ldsm4(af[mt], aAddr + mt * 16 * A_LDA * 2);
#pragma unroll
            for (int p = 0; p < 2; p++) ldsm4t(bd[p], bAddr + p * 32);
#pragma unroll
            for (int nt = 0; nt < 4; nt++) {
                const uint32_t* b = &bd[nt >> 1][(nt & 1) * 2];
#pragma unroll
                for (int mt = 0; mt < 4; mt++) mma16(cd[mt][nt], af[mt], b);
            }
        }
    }
#undef G2_ISSUE
    /* fused combine: scale by routing weight, atomic accumulate into out */
#pragma unroll
    for (int mt = 0; mt < 4; mt++) {
#pragma unroll
        for (int h = 0; h < 2; h++) {
            const int lr = wm * 64 + mt * 16 + gid + h * 8;
            const int p = prs[lr];
            if (p >= 0) {
                const float wv = g_topkw[p];
                const int tok = p >> 3;
                float* dst = out + (size_t)tok * HDIM + n0 + wn * 32;
#pragma unroll
                for (int nt = 0; nt < 4; nt++) {
                    atomicAdd(dst + nt * 8 + 2 * tig,     wv * cd[mt][nt][h * 2 + 0]);
                    atomicAdd(dst + nt * 8 + 2 * tig + 1, wv * cd[mt][nt][h * 2 + 1]);
                }
            }
        }
    }
}

/* ---------------- launch ---------------- */
extern "C" void kernel_launch(void* const* d_in, const int* /*in_sizes*/, int /*n_in*/,
                              void* d_out, int /*out_size*/) {
    const float* x   = (const float*)d_in[0];
    const float* gw  = (const float*)d_in[1];
    const float* wgt = (const float*)d_in[2];
    const float* wup = (const float*)d_in[3];
    const float* wdn = (const float*)d_in[4];
    float* out = (float*)d_out;

    cudaFuncSetAttribute(k_gemm1, cudaFuncAttributeMaxDynamicSharedMemorySize, G_SMEM);
    cudaFuncSetAttribute(k_gemm2, cudaFuncAttributeMaxDynamicSharedMemorySize, G_SMEM);

    const size_t nW = (size_t)NEXP * HDIM * IDIM / 8;
    const size_t nX = (size_t)TTOK * HDIM / 8;
    const size_t nA = (size_t)NPAIR * IDIM / 8;

    k_zero_out<<<TTOK * HDIM / 4 / 256, 256>>>((float4*)out);
    k_zero_counts<<<1, 64>>>();
    k_cvt<<<(unsigned)((nW + 255) / 256), 256>>>((const float4*)wgt, 0, nW);
    k_cvt<<<(unsigned)((nW + 255) / 256), 256>>>((const float4*)wup, 1, nW);
    k_cvt<<<(unsigned)((nW + 255) / 256), 256>>>((const float4*)wdn, 2, nW);
    k_cvt<<<(unsigned)((nX + 255) / 256), 256>>>((const float4*)x,   3, nX);
    k_router<<<TTOK / 64, 256>>>(x, gw);
    k_topk<<<TTOK / 256, 256>>>();
    k_scan<<<1, 1>>>();
    k_gemm1<<<dim3(IDIM / 128, CAP / 128, NEXP * 2), 256, G_SMEM>>>();
    k_silu<<<(unsigned)((nA + 255) / 256), 256>>>();
    k_gemm2<<<dim3(HDIM / 128, CAP / 128, NEXP), 256, G_SMEM>>>(out);
}

// round 13
// speedup vs baseline: 1.1108x; 1.1108x over previous
#include <cuda_runtime.h>
#include <cuda_fp16.h>
#include <math.h>
#include <stdint.h>

#define TTOK 4096
#define HDIM 2048
#define NEXP 64
#define TOPK 8
#define IDIM 768
#define NPAIR (TTOK * TOPK)
#define CAP   TTOK

/* ---------------- scratch ---------------- */
__device__ float g_logits[TTOK * NEXP];
__device__ float g_topkw[NPAIR];
__device__ int   g_counts[NEXP];
__device__ int   g_offsets[NEXP];
__device__ int   g_bucket[NEXP * CAP];
__device__ uint4 g_act4[(size_t)NPAIR * IDIM / 8];          /* fp16 silu(g)*u     */
__device__ uint4 g_gb[(size_t)NPAIR * IDIM / 8];            /* fp16 gate result   */
__device__ uint4 g_ub[(size_t)NPAIR * IDIM / 8];            /* fp16 up result     */
__device__ uint4 g_xh[(size_t)TTOK * HDIM / 8];             /* fp16 tokens        */
__device__ uint4 g_wgh[(size_t)NEXP * HDIM * IDIM / 8];     /* fp16 w_gate        */
__device__ uint4 g_wuh[(size_t)NEXP * HDIM * IDIM / 8];     /* fp16 w_up          */
__device__ uint4 g_wdh[(size_t)NEXP * IDIM * HDIM / 8];     /* fp16 w_down        */

#define LD4(p) (*reinterpret_cast<const float4*>(p))

/* ---------------- helpers ---------------- */
__device__ __forceinline__ uint32_t smem_u32(const void* p) {
    uint32_t a;
    asm("{ .reg .u64 t; cvta.to.shared.u64 t, %1; cvt.u32.u64 %0, t; }" : "=r"(a) : "l"(p));
    return a;
}
__device__ __forceinline__ uint32_t pk2(float x, float y) {
    __half2 h = __floats2half2_rn(x, y);
    return *reinterpret_cast<uint32_t*>(&h);
}
__device__ __forceinline__ void ldsm4(uint32_t* r, uint32_t addr) {
    asm volatile("ldmatrix.sync.aligned.m8n8.x4.shared.b16 {%0,%1,%2,%3}, [%4];"
                 : "=r"(r[0]), "=r"(r[1]), "=r"(r[2]), "=r"(r[3]) : "r"(addr));
}
__device__ __forceinline__ void ldsm4t(uint32_t* r, uint32_t addr) {
    asm volatile("ldmatrix.sync.aligned.m8n8.x4.trans.shared.b16 {%0,%1,%2,%3}, [%4];"
                 : "=r"(r[0]), "=r"(r[1]), "=r"(r[2]), "=r"(r[3]) : "r"(addr));
}
__device__ __forceinline__ void mma16(float* d, const uint32_t* a, const uint32_t* b) {
    asm volatile(
        "mma.sync.aligned.m16n8k16.row.col.f32.f16.f16.f32 "
        "{%0,%1,%2,%3}, {%4,%5,%6,%7}, {%8,%9}, {%0,%1,%2,%3};"
        : "+f"(d[0]), "+f"(d[1]), "+f"(d[2]), "+f"(d[3])
        : "r"(a[0]), "r"(a[1]), "r"(a[2]), "r"(a[3]), "r"(b[0]), "r"(b[1]));
}
__device__ __forceinline__ void cpa16(uint32_t sdst, const void* gsrc, uint32_t sz) {
    asm volatile("cp.async.cg.shared.global [%0], [%1], 16, %2;"
                 :: "r"(sdst), "l"(gsrc), "r"(sz) : "memory");
}
__device__ __forceinline__ void cpa_commit() {
    asm volatile("cp.async.commit_group;" ::: "memory");
}
__device__ __forceinline__ void cpa_wait2() {
    asm volatile("cp.async.wait_group 2;" ::: "memory");
}

/* smem tiles (halves): A[128][24] (48B rows), B[16][136] (272B rows).
   4 pipeline stages, wait_group 2. */
#define A_LDA 24
#define B_LDB 136
#define A_HALVES (128 * A_LDA)
#define B_HALVES (16 * B_LDB)
#define G_STAGE_H (A_HALVES + B_HALVES)          /* 5248 halves */
#define G_SMEM (512 + 4 * G_STAGE_H * 2)         /* ~42.5KB -> 2 CTAs/SM */

/* ---------------- small kernels ---------------- */
__global__ void k_zero_counts() { if (threadIdx.x < NEXP) g_counts[threadIdx.x] = 0; }

__global__ void k_zero_out(float4* __restrict__ out) {
    size_t i = (size_t)blockIdx.x * blockDim.x + threadIdx.x;
    if (i < (size_t)TTOK * HDIM / 4) out[i] = make_float4(0.f, 0.f, 0.f, 0.f);
}

/* fp32 -> fp16 bulk convert. dst selected DEVICE-SIDE (host shadow-symbol trap). */
__global__ void __launch_bounds__(256) k_cvt(const float4* __restrict__ src,
                                             int which, size_t n8) {
    size_t i = (size_t)blockIdx.x * blockDim.x + threadIdx.x;
    if (i >= n8) return;
    uint4* dst = (which == 0) ? g_wgh : (which == 1) ? g_wuh : (which == 2) ? g_wdh : g_xh;
    float4 a = src[2 * i], b = src[2 * i + 1];
    dst[i] = make_uint4(pk2(a.x, a.y), pk2(a.z, a.w), pk2(b.x, b.y), pk2(b.z, b.w));
}

/* elementwise act = silu(g) * u, fp16 in/out, 8 elems/thread */
__global__ void __launch_bounds__(256) k_silu() {
    size_t i = (size_t)blockIdx.x * blockDim.x + threadIdx.x;
    if (i >= (size_t)NPAIR * IDIM / 8) return;
    uint4 gv = g_gb[i], uv = g_ub[i];
    const uint32_t* gw = &gv.x;
    const uint32_t* uw = &uv.x;
    uint4 o;
    uint32_t* ow = &o.x;
#pragma unroll
    for (int j = 0; j < 4; j++) {
        __half2 gh = *reinterpret_cast<const __half2*>(&gw[j]);
        __half2 uh = *reinterpret_cast<const __half2*>(&uw[j]);
        float2 gf = __half22float2(gh), uf = __half22float2(uh);
        float o0 = gf.x / (1.f + expf(-gf.x)) * uf.x;
        float o1 = gf.y / (1.f + expf(-gf.y)) * uf.y;
        ow[j] = pk2(o0, o1);
    }
    g_act4[i] = o;
}

__global__ void __launch_bounds__(256) k_router(const float* __restrict__ x,
                                                const float* __restrict__ gw) {
    __shared__ float As[16][64];
    __shared__ float Bs[16][64];
    const int t = threadIdx.x;
    const int m0 = blockIdx.x * 64;
    const int tx = t & 15, ty = t >> 4;
    const int mload = t >> 2;
    const int kq = (t & 3) * 4;
    float acc[4][4] = {};
    for (int k0 = 0; k0 < HDIM; k0 += 16) {
        float4 av = LD4(x + (size_t)(m0 + mload) * HDIM + k0 + kq);
        float4 bv = LD4(gw + (size_t)mload * HDIM + k0 + kq);
        __syncthreads();
        As[kq + 0][mload] = av.x; As[kq + 1][mload] = av.y;
        As[kq + 2][mload] = av.z; As[kq + 3][mload] = av.w;
        Bs[kq + 0][mload] = bv.x; Bs[kq + 1][mload] = bv.y;
        Bs[kq + 2][mload] = bv.z; Bs[kq + 3][mload] = bv.w;
        __syncthreads();
#pragma unroll
        for (int k = 0; k < 16; k++) {
            float4 a = LD4(&As[k][ty * 4]);
            float4 b = LD4(&Bs[k][tx * 4]);
            float ax[4] = {a.x, a.y, a.z, a.w};
            float bx[4] = {b.x, b.y, b.z, b.w};
#pragma unroll
            for (int i = 0; i < 4; i++)
#pragma unroll
                for (int j = 0; j < 4; j++)
                    acc[i][j] = fmaf(ax[i], bx[j], acc[i][j]);
        }
    }
#pragma unroll
    for (int i = 0; i < 4; i++)
#pragma unroll
        for (int j = 0; j < 4; j++)
            g_logits[(size_t)(m0 + ty * 4 + i) * NEXP + tx * 4 + j] = acc[i][j];
}

__global__ void k_topk() {
    int t = blockIdx.x * blockDim.x + threadIdx.x;
    if (t >= TTOK) return;
    float l[NEXP];
    for (int e = 0; e < NEXP; e++) l[e] = g_logits[(size_t)t * NEXP + e];
    float vals[TOPK]; int ids[TOPK];
    for (int k = 0; k < TOPK; k++) {
        float best = -3.4e38f; int bi = 0;
        for (int e = 0; e < NEXP; e++)
            if (l[e] > best) { best = l[e]; bi = e; }
        vals[k] = best; ids[k] = bi; l[bi] = -3.4e38f;
    }
    float m = vals[0], s = 0.f, wv[TOPK];
    for (int k = 0; k < TOPK; k++) { wv[k] = expf(vals[k] - m); s += wv[k]; }
    float inv = 1.f / s;
    for (int k = 0; k < TOPK; k++) {
        g_topkw[t * TOPK + k] = wv[k] * inv;
        int e = ids[k];
        int pos = atomicAdd(&g_counts[e], 1);
        g_bucket[e * CAP + pos] = t * TOPK + k;
    }
}

__global__ void k_scan() {
    int s = 0;
    for (int e = 0; e < NEXP; e++) { g_offsets[e] = s; s += g_counts[e]; }
}

/* ======= stage 4: gate OR up fp16 HMMA, 4-stage pipe, m-tiles innermost ===== */
__global__ void __launch_bounds__(256, 2)
k_gemm1() {
    extern __shared__ char smraw[];
    const int e = blockIdx.z >> 1;
    const int which = blockIdx.z & 1;
    const int rows = g_counts[e];
    const int m0 = blockIdx.x * 128;          /* m innermost -> wave shares B panel */
    if (m0 >= rows) return;
    const int n0 = blockIdx.y * 128;
    const int t = threadIdx.x, w = t >> 5, lane = t & 31;
    const int gid = lane >> 2, tig = lane & 3;
    const int wm = w >> 2, wn = w & 3;

    int* toks = (int*)smraw;
    __half* buf = (__half*)(smraw + 512);
    if (t < 128) {
        int r = m0 + t;
        toks[t] = (r < rows) ? (g_bucket[e * CAP + r] >> 3) : -1;
    }
    __syncthreads();

    const __half* xh = (const __half*)g_xh;
    const __half* wh = (const __half*)(which ? g_wuh : g_wgh) + (size_t)e * HDIM * IDIM;

    const int am = t >> 1, ah = (t & 1) * 8;
    const int tokA = toks[am];
    const uint32_t asz = (tokA >= 0) ? 16u : 0u;
    const __half* aptr = xh + (size_t)(tokA >= 0 ? tokA : 0) * HDIM;
    const int bk = t >> 4, bn = (t & 15) * 8;
    const __half* bptr = wh + (size_t)bk * IDIM + n0 + bn;

    const uint32_t sb = smem_u32(buf);
    const uint32_t aDst = sb + (uint32_t)(am * A_LDA + ah) * 2;
    const uint32_t bDst = sb + (uint32_t)(A_HALVES + bk * B_LDB + bn) * 2;

    const int KT = HDIM / 16;
#define G1_ISSUE(s) { \
        const uint32_t so = (uint32_t)((s) & 3) * (G_STAGE_H * 2); \
        const int kb = (s) * 16; \
        cpa16(aDst + so, aptr + kb + ah, asz); \
        cpa16(bDst + so, bptr + (size_t)kb * IDIM, 16u); \
    }
    G1_ISSUE(0); cpa_commit();
    G1_ISSUE(1); cpa_commit();
    G1_ISSUE(2); cpa_commit();

    float cg[4][4][4] = {};
    const int aRow = wm * 64 + (lane & 15);
    const int aK   = (lane >> 4) * 8;
    const int bRow = lane & 15;
    const int bOct = (lane >> 4) * 8;

    for (int kt = 0; kt < KT; kt++) {
        cpa_wait2();
        __syncthreads();
        if (kt + 3 < KT) G1_ISSUE(kt + 3);
        cpa_commit();
        __half* stc = buf + (kt & 3) * G_STAGE_H;
        const uint32_t aAddr = smem_u32(stc + aRow * A_LDA + aK);
        const uint32_t bAddr = smem_u32(stc + A_HALVES + bRow * B_LDB + wn * 32 + bOct);
        uint32_t af[4][4], bg[2][4];
#pragma unroll
        for (int mt = 0; mt < 4; mt++) ldsm4(af[mt], aAddr + mt * 16 * A_LDA * 2);
#pragma unroll
        for (int p = 0; p < 2; p++) ldsm4t(bg[p], bAddr + p * 32);
#pragma unroll
        for (int nt = 0; nt < 4; nt++) {
            const uint32_t* b = &bg[nt >> 1][(nt & 1) * 2];
#pragma unroll
            for (int mt = 0; mt < 4; mt++) mma16(cg[mt][nt], af[mt], b);
        }
    }
#undef G1_ISSUE
    /* epilogue -> raw fp16 gate/up buffer */
    __half* gout = (__half*)(which ? g_ub : g_gb);
    const int off = g_offsets[e];
#pragma unroll
    for (int mt = 0; mt < 4; mt++) {
#pragma unroll
        for (int h = 0; h < 2; h++) {
            const int row = m0 + wm * 64 + mt * 16 + gid + h * 8;
            if (row < rows) {
                __half* dst = gout + (size_t)(off + row) * IDIM + n0 + wn * 32;
#pragma unroll
                for (int nt = 0; nt < 4; nt++)
                    *reinterpret_cast<uint32_t*>(dst + nt * 8 + 2 * tig) =
                        pk2(cg[mt][nt][h * 2 + 0], cg[mt][nt][h * 2 + 1]);
            }
        }
    }
}

/* ===== stage 5: down-proj fp16 HMMA + fused combine, 4-stage pipe ===== */
__global__ void __launch_bounds__(256, 2)
k_gemm2(float* __restrict__ out) {
    extern __shared__ char smraw[];
    const int e = blockIdx.z;
    const int rows = g_counts[e];
    const int m0 = blockIdx.x * 128;          /* m innermost */
    if (m0 >= rows) return;
    const int n0 = blockIdx.y * 128;
    const int t = threadIdx.x, w = t >> 5, lane = t & 31;
    const int gid = lane >> 2, tig = lane & 3;
    const int wm = w >> 2, wn = w & 3;
    const int off = g_offsets[e];

    int* prs = (int*)smraw;
    __half* buf = (__half*)(smraw + 512);
    if (t < 128) {
        int r = m0 + t;
        prs[t] = (r < rows) ? g_bucket[e * CAP + r] : -1;
    }
    __syncthreads();

    const __half* gact = (const __half*)g_act4;
    const __half* wdh  = (const __half*)g_wdh + (size_t)e * IDIM * HDIM;

    const int am = t >> 1, ah = (t & 1) * 8;
    const uint32_t asz = (m0 + am < rows) ? 16u : 0u;
    const __half* aptr = gact + (size_t)(off + m0 + ((m0 + am < rows) ? am : 0)) * IDIM;
    const int bk = t >> 4, bn = (t & 15) * 8;
    const __half* bptr = wdh + (size_t)bk * HDIM + n0 + bn;

    const uint32_t sb = smem_u32(buf);
    const uint32_t aDst = sb + (uint32_t)(am * A_LDA + ah) * 2;
    const uint32_t bDst = sb + (uint32_t)(A_HALVES + bk * B_LDB + bn) * 2;

    const int KT = IDIM / 16;
#define G2_ISSUE(s) { \
        const uint32_t so = (uint32_t)((s) & 3) * (G_STAGE_H * 2); \
        const int kb = (s) * 16; \
        cpa16(aDst + so, aptr + kb + ah, asz); \
        cpa16(bDst + so, bptr + (size_t)kb * HDIM, 16u); \
    }
    G2_ISSUE(0); cpa_commit();
    G2_ISSUE(1); cpa_commit();
    G2_ISSUE(2); cpa_commit();

    float cd[4][4][4] = {};
    const int aRow = wm * 64 + (lane & 15);
    const int aK   = (lane >> 4) * 8;
    const int bRow = lane & 15;
    const int bOct = (lane >> 4) * 8;

    for (int kt = 0; kt < KT; kt++) {
        cpa_wait2();
        __syncthreads();
        if (kt + 3 < KT) G2_ISSUE(kt + 3);
        cpa_commit();
        __half* stc = buf + (kt & 3) * G_STAGE_H;
        const uint32_t aAddr = smem_u32(stc + aRow * A_LDA + aK);
        const uint32_t bAddr = smem_u32(stc + A_HALVES + bRow * B_LDB + wn * 32 + bOct);
        uint32_t af[4][4], bd[2][4];
#pragma unroll
        for (int mt = 0; mt < 4; mt++) ldsm4(af[mt], aAddr + mt * 16 * A_LDA * 2);
#pragma unroll
        for (int p = 0; p < 2; p++) ldsm4t(bd[p], bAddr + p * 32);
#pragma unroll
        for (int nt = 0; nt < 4; nt++) {
            const uint32_t* b = &bd[nt >> 1][(nt & 1) * 2];
#pragma unroll
            for (int mt = 0; mt < 4; mt++) mma16(cd[mt][nt], af[mt], b);
        }
    }
#undef G2_ISSUE
    /* fused combine: scale by routing weight, atomic accumulate into out */
#pragma unroll
    for (int mt = 0; mt < 4; mt++) {
#pragma unroll
        for (int h = 0; h < 2; h++) {
            const int lr = wm * 64 + mt * 16 + gid + h * 8;
            const int p = prs[lr];
            if (p >= 0) {
                const float wv = g_topkw[p];
                const int tok = p >> 3;
                float* dst = out + (size_t)tok * HDIM + n0 + wn * 32;
#pragma unroll
                for (int nt = 0; nt < 4; nt++) {
                    atomicAdd(dst + nt * 8 + 2 * tig,     wv * cd[mt][nt][h * 2 + 0]);
                    atomicAdd(dst + nt * 8 + 2 * tig + 1, wv * cd[mt][nt][h * 2 + 1]);
                }
            }
        }
    }
}

/* ---------------- launch ---------------- */
extern "C" void kernel_launch(void* const* d_in, const int* /*in_sizes*/, int /*n_in*/,
                              void* d_out, int /*out_size*/) {
    const float* x   = (const float*)d_in[0];
    const float* gw  = (const float*)d_in[1];
    const float* wgt = (const float*)d_in[2];
    const float* wup = (const float*)d_in[3];
    const float* wdn = (const float*)d_in[4];
    float* out = (float*)d_out;

    cudaFuncSetAttribute(k_gemm1, cudaFuncAttributeMaxDynamicSharedMemorySize, G_SMEM);
    cudaFuncSetAttribute(k_gemm2, cudaFuncAttributeMaxDynamicSharedMemorySize, G_SMEM);

    const size_t nW = (size_t)NEXP * HDIM * IDIM / 8;
    const size_t nX = (size_t)TTOK * HDIM / 8;
    const size_t nA = (size_t)NPAIR * IDIM / 8;

    k_zero_out<<<TTOK * HDIM / 4 / 256, 256>>>((float4*)out);
    k_zero_counts<<<1, 64>>>();
    k_cvt<<<(unsigned)((nW + 255) / 256), 256>>>((const float4*)wgt, 0, nW);
    k_cvt<<<(unsigned)((nW + 255) / 256), 256>>>((const float4*)wup, 1, nW);
    k_cvt<<<(unsigned)((nW + 255) / 256), 256>>>((const float4*)wdn, 2, nW);
    k_cvt<<<(unsigned)((nX + 255) / 256), 256>>>((const float4*)x,   3, nX);
    k_router<<<TTOK / 64, 256>>>(x, gw);
    k_topk<<<TTOK / 256, 256>>>();
    k_scan<<<1, 1>>>();
    k_gemm1<<<dim3(CAP / 128, IDIM / 128, NEXP * 2), 256, G_SMEM>>>();
    k_silu<<<(unsigned)((nA + 255) / 256), 256>>>();
    k_gemm2<<<dim3(CAP / 128, HDIM / 128, NEXP), 256, G_SMEM>>>(out);
}

// round 14
// speedup vs baseline: 1.1189x; 1.0072x over previous
#include <cuda_runtime.h>
#include <cuda_fp16.h>
#include <math.h>
#include <stdint.h>

#define TTOK 4096
#define HDIM 2048
#define NEXP 64
#define TOPK 8
#define IDIM 768
#define NPAIR (TTOK * TOPK)
#define CAP   TTOK

/* ---------------- scratch ---------------- */
__device__ float g_logits[TTOK * NEXP];
__device__ float g_topkw[NPAIR];
__device__ int   g_counts[NEXP];
__device__ int   g_offsets[NEXP];
__device__ int   g_bucket[NEXP * CAP];
__device__ uint4 g_act4[(size_t)NPAIR * IDIM / 8];          /* fp16 silu(g)*u     */
__device__ uint4 g_gb[(size_t)NPAIR * IDIM / 8];            /* fp16 gate result   */
__device__ uint4 g_ub[(size_t)NPAIR * IDIM / 8];            /* fp16 up result     */
__device__ uint4 g_xh[(size_t)TTOK * HDIM / 8];             /* fp16 tokens        */
__device__ uint4 g_wgh[(size_t)NEXP * HDIM * IDIM / 8];     /* fp16 w_gate        */
__device__ uint4 g_wuh[(size_t)NEXP * HDIM * IDIM / 8];     /* fp16 w_up          */
__device__ uint4 g_wdh[(size_t)NEXP * IDIM * HDIM / 8];     /* fp16 w_down        */

#define LD4(p) (*reinterpret_cast<const float4*>(p))

/* ---------------- helpers ---------------- */
__device__ __forceinline__ uint32_t smem_u32(const void* p) {
    uint32_t a;
    asm("{ .reg .u64 t; cvta.to.shared.u64 t, %1; cvt.u32.u64 %0, t; }" : "=r"(a) : "l"(p));
    return a;
}
__device__ __forceinline__ uint32_t pk2(float x, float y) {
    __half2 h = __floats2half2_rn(x, y);
    return *reinterpret_cast<uint32_t*>(&h);
}
__device__ __forceinline__ void ldsm4(uint32_t* r, uint32_t addr) {
    asm volatile("ldmatrix.sync.aligned.m8n8.x4.shared.b16 {%0,%1,%2,%3}, [%4];"
                 : "=r"(r[0]), "=r"(r[1]), "=r"(r[2]), "=r"(r[3]) : "r"(addr));
}
__device__ __forceinline__ void ldsm4t(uint32_t* r, uint32_t addr) {
    asm volatile("ldmatrix.sync.aligned.m8n8.x4.trans.shared.b16 {%0,%1,%2,%3}, [%4];"
                 : "=r"(r[0]), "=r"(r[1]), "=r"(r[2]), "=r"(r[3]) : "r"(addr));
}
__device__ __forceinline__ void mma16(float* d, const uint32_t* a, const uint32_t* b) {
    asm volatile(
        "mma.sync.aligned.m16n8k16.row.col.f32.f16.f16.f32 "
        "{%0,%1,%2,%3}, {%4,%5,%6,%7}, {%8,%9}, {%0,%1,%2,%3};"
        : "+f"(d[0]), "+f"(d[1]), "+f"(d[2]), "+f"(d[3])
        : "r"(a[0]), "r"(a[1]), "r"(a[2]), "r"(a[3]), "r"(b[0]), "r"(b[1]));
}
__device__ __forceinline__ void cpa16(uint32_t sdst, const void* gsrc, uint32_t sz) {
    asm volatile("cp.async.cg.shared.global [%0], [%1], 16, %2;"
                 :: "r"(sdst), "l"(gsrc), "r"(sz) : "memory");
}
__device__ __forceinline__ void cpa_commit() {
    asm volatile("cp.async.commit_group;" ::: "memory");
}
__device__ __forceinline__ void cpa_wait2() {
    asm volatile("cp.async.wait_group 2;" ::: "memory");
}

/* smem tiles (halves): A[128][24] (48B rows), B[16][136] (272B rows).
   4 pipeline stages, wait_group 2. */
#define A_LDA 24
#define B_LDB 136
#define A_HALVES (128 * A_LDA)
#define B_HALVES (16 * B_LDB)
#define G_STAGE_H (A_HALVES + B_HALVES)          /* 5248 halves */
#define G_SMEM (512 + 4 * G_STAGE_H * 2)         /* ~42.5KB -> 2 CTAs/SM */

/* ---------------- small kernels ---------------- */
__global__ void k_zero_counts() { if (threadIdx.x < NEXP) g_counts[threadIdx.x] = 0; }

__global__ void k_zero_out(float4* __restrict__ out) {
    size_t i = (size_t)blockIdx.x * blockDim.x + threadIdx.x;
    if (i < (size_t)TTOK * HDIM / 4) out[i] = make_float4(0.f, 0.f, 0.f, 0.f);
}

/* fp32 -> fp16 bulk convert. dst selected DEVICE-SIDE (host shadow-symbol trap). */
__global__ void __launch_bounds__(256) k_cvt(const float4* __restrict__ src,
                                             int which, size_t n8) {
    size_t i = (size_t)blockIdx.x * blockDim.x + threadIdx.x;
    if (i >= n8) return;
    uint4* dst = (which == 0) ? g_wgh : (which == 1) ? g_wuh : (which == 2) ? g_wdh : g_xh;
    float4 a = src[2 * i], b = src[2 * i + 1];
    dst[i] = make_uint4(pk2(a.x, a.y), pk2(a.z, a.w), pk2(b.x, b.y), pk2(b.z, b.w));
}

/* elementwise act = silu(g) * u, fp16 in/out, 8 elems/thread */
__global__ void __launch_bounds__(256) k_silu() {
    size_t i = (size_t)blockIdx.x * blockDim.x + threadIdx.x;
    if (i >= (size_t)NPAIR * IDIM / 8) return;
    uint4 gv = g_gb[i], uv = g_ub[i];
    const uint32_t* gw = &gv.x;
    const uint32_t* uw = &uv.x;
    uint4 o;
    uint32_t* ow = &o.x;
#pragma unroll
    for (int j = 0; j < 4; j++) {
        __half2 gh = *reinterpret_cast<const __half2*>(&gw[j]);
        __half2 uh = *reinterpret_cast<const __half2*>(&uw[j]);
        float2 gf = __half22float2(gh), uf = __half22float2(uh);
        float o0 = gf.x / (1.f + expf(-gf.x)) * uf.x;
        float o1 = gf.y / (1.f + expf(-gf.y)) * uf.y;
        ow[j] = pk2(o0, o1);
    }
    g_act4[i] = o;
}

__global__ void __launch_bounds__(256) k_router(const float* __restrict__ x,
                                                const float* __restrict__ gw) {
    __shared__ float As[16][64];
    __shared__ float Bs[16][64];
    const int t = threadIdx.x;
    const int m0 = blockIdx.x * 64;
    const int tx = t & 15, ty = t >> 4;
    const int mload = t >> 2;
    const int kq = (t & 3) * 4;
    float acc[4][4] = {};
    for (int k0 = 0; k0 < HDIM; k0 += 16) {
        float4 av = LD4(x + (size_t)(m0 + mload) * HDIM + k0 + kq);
        float4 bv = LD4(gw + (size_t)mload * HDIM + k0 + kq);
        __syncthreads();
        As[kq + 0][mload] = av.x; As[kq + 1][mload] = av.y;
        As[kq + 2][mload] = av.z; As[kq + 3][mload] = av.w;
        Bs[kq + 0][mload] = bv.x; Bs[kq + 1][mload] = bv.y;
        Bs[kq + 2][mload] = bv.z; Bs[kq + 3][mload] = bv.w;
        __syncthreads();
#pragma unroll
        for (int k = 0; k < 16; k++) {
            float4 a = LD4(&As[k][ty * 4]);
            float4 b = LD4(&Bs[k][tx * 4]);
            float ax[4] = {a.x, a.y, a.z, a.w};
            float bx[4] = {b.x, b.y, b.z, b.w};
#pragma unroll
            for (int i = 0; i < 4; i++)
#pragma unroll
                for (int j = 0; j < 4; j++)
                    acc[i][j] = fmaf(ax[i], bx[j], acc[i][j]);
        }
    }
#pragma unroll
    for (int i = 0; i < 4; i++)
#pragma unroll
        for (int j = 0; j < 4; j++)
            g_logits[(size_t)(m0 + ty * 4 + i) * NEXP + tx * 4 + j] = acc[i][j];
}

__global__ void k_topk() {
    int t = blockIdx.x * blockDim.x + threadIdx.x;
    if (t >= TTOK) return;
    float l[NEXP];
    for (int e = 0; e < NEXP; e++) l[e] = g_logits[(size_t)t * NEXP + e];
    float vals[TOPK]; int ids[TOPK];
    for (int k = 0; k < TOPK; k++) {
        float best = -3.4e38f; int bi = 0;
        for (int e = 0; e < NEXP; e++)
            if (l[e] > best) { best = l[e]; bi = e; }
        vals[k] = best; ids[k] = bi; l[bi] = -3.4e38f;
    }
    float m = vals[0], s = 0.f, wv[TOPK];
    for (int k = 0; k < TOPK; k++) { wv[k] = expf(vals[k] - m); s += wv[k]; }
    float inv = 1.f / s;
    for (int k = 0; k < TOPK; k++) {
        g_topkw[t * TOPK + k] = wv[k] * inv;
        int e = ids[k];
        int pos = atomicAdd(&g_counts[e], 1);
        g_bucket[e * CAP + pos] = t * TOPK + k;
    }
}

__global__ void k_scan() {
    int s = 0;
    for (int e = 0; e < NEXP; e++) { g_offsets[e] = s; s += g_counts[e]; }
}

/* ======= stage 4: gate OR up fp16 HMMA, 4-stage pipe, m-tiles innermost ===== */
__global__ void __launch_bounds__(256, 2)
k_gemm1() {
    extern __shared__ char smraw[];
    const int e = blockIdx.z >> 1;
    const int which = blockIdx.z & 1;
    const int rows = g_counts[e];
    const int m0 = blockIdx.x * 128;
    if (m0 >= rows) return;
    const int n0 = blockIdx.y * 128;
    const int t = threadIdx.x, w = t >> 5, lane = t & 31;
    const int gid = lane >> 2, tig = lane & 3;
    const int wm = w >> 2, wn = w & 3;

    int* toks = (int*)smraw;
    __half* buf = (__half*)(smraw + 512);
    if (t < 128) {
        int r = m0 + t;
        toks[t] = (r < rows) ? (g_bucket[e * CAP + r] >> 3) : -1;
    }
    __syncthreads();

    const __half* xh = (const __half*)g_xh;
    const __half* wh = (const __half*)(which ? g_wuh : g_wgh) + (size_t)e * HDIM * IDIM;

    const int am = t >> 1, ah = (t & 1) * 8;
    const int tokA = toks[am];
    const uint32_t asz = (tokA >= 0) ? 16u : 0u;
    const __half* aptr = xh + (size_t)(tokA >= 0 ? tokA : 0) * HDIM;
    const int bk = t >> 4, bn = (t & 15) * 8;
    const __half* bptr = wh + (size_t)bk * IDIM + n0 + bn;

    const uint32_t sb = smem_u32(buf);
    const uint32_t aDst = sb + (uint32_t)(am * A_LDA + ah) * 2;
    const uint32_t bDst = sb + (uint32_t)(A_HALVES + bk * B_LDB + bn) * 2;

    const int KT = HDIM / 16;
#define G1_ISSUE(s) { \
        const uint32_t so = (uint32_t)((s) & 3) * (G_STAGE_H * 2); \
        const int kb = (s) * 16; \
        cpa16(aDst + so, aptr + kb + ah, asz); \
        cpa16(bDst + so, bptr + (size_t)kb * IDIM, 16u); \
    }
    G1_ISSUE(0); cpa_commit();
    G1_ISSUE(1); cpa_commit();
    G1_ISSUE(2); cpa_commit();

    float cg[4][4][4] = {};
    const int aRow = wm * 64 + (lane & 15);
    const int aK   = (lane >> 4) * 8;
    const int bRow = lane & 15;
    const int bOct = (lane >> 4) * 8;

    for (int kt = 0; kt < KT; kt++) {
        cpa_wait2();
        __syncthreads();
        if (kt + 3 < KT) G1_ISSUE(kt + 3);
        cpa_commit();
        __half* stc = buf + (kt & 3) * G_STAGE_H;
        const uint32_t aAddr = smem_u32(stc + aRow * A_LDA + aK);
        const uint32_t bAddr = smem_u32(stc + A_HALVES + bRow * B_LDB + wn * 32 + bOct);
        uint32_t af[4][4], bg[2][4];
#pragma unroll
        for (int mt = 0; mt < 4; mt++) ldsm4(af[mt], aAddr + mt * 16 * A_LDA * 2);
#pragma unroll
        for (int p = 0; p < 2; p++) ldsm4t(bg[p], bAddr + p * 32);
#pragma unroll
        for (int nt = 0; nt < 4; nt++) {
            const uint32_t* b = &bg[nt >> 1][(nt & 1) * 2];
#pragma unroll
            for (int mt = 0; mt < 4; mt++) mma16(cg[mt][nt], af[mt], b);
        }
    }
#undef G1_ISSUE
    __half* gout = (__half*)(which ? g_ub : g_gb);
    const int off = g_offsets[e];
#pragma unroll
    for (int mt = 0; mt < 4; mt++) {
#pragma unroll
        for (int h = 0; h < 2; h++) {
            const int row = m0 + wm * 64 + mt * 16 + gid + h * 8;
            if (row < rows) {
                __half* dst = gout + (size_t)(off + row) * IDIM + n0 + wn * 32;
#pragma unroll
                for (int nt = 0; nt < 4; nt++)
                    *reinterpret_cast<uint32_t*>(dst + nt * 8 + 2 * tig) =
                        pk2(cg[mt][nt][h * 2 + 0], cg[mt][nt][h * 2 + 1]);
            }
        }
    }
}

/* ===== stage 5: down-proj fp16 HMMA + fused combine, 4-stage pipe ===== */
__global__ void __launch_bounds__(256, 2)
k_gemm2(float* __restrict__ out) {
    extern __shared__ char smraw[];
    const int e = blockIdx.z;
    const int rows = g_counts[e];
    const int m0 = blockIdx.x * 128;
    if (m0 >= rows) return;
    const int n0 = blockIdx.y * 128;
    const int t = threadIdx.x, w = t >> 5, lane = t & 31;
    const int gid = lane >> 2, tig = lane & 3;
    const int wm = w >> 2, wn = w & 3;
    const int off = g_offsets[e];

    int* prs = (int*)smraw;
    __half* buf = (__half*)(smraw + 512);
    if (t < 128) {
        int r = m0 + t;
        prs[t] = (r < rows) ? g_bucket[e * CAP + r] : -1;
    }
    __syncthreads();

    const __half* gact = (const __half*)g_act4;
    const __half* wdh  = (const __half*)g_wdh + (size_t)e * IDIM * HDIM;

    const int am = t >> 1, ah = (t & 1) * 8;
    const uint32_t asz = (m0 + am < rows) ? 16u : 0u;
    const __half* aptr = gact + (size_t)(off + m0 + ((m0 + am < rows) ? am : 0)) * IDIM;
    const int bk = t >> 4, bn = (t & 15) * 8;
    const __half* bptr = wdh + (size_t)bk * HDIM + n0 + bn;

    const uint32_t sb = smem_u32(buf);
    const uint32_t aDst = sb + (uint32_t)(am * A_LDA + ah) * 2;
    const uint32_t bDst = sb + (uint32_t)(A_HALVES + bk * B_LDB + bn) * 2;

    const int KT = IDIM / 16;
#define G2_ISSUE(s) { \
        const uint32_t so = (uint32_t)((s) & 3) * (G_STAGE_H * 2); \
        const int kb = (s) * 16; \
        cpa16(aDst + so, aptr + kb + ah, asz); \
        cpa16(bDst + so, bptr + (size_t)kb * HDIM, 16u); \
    }
    G2_ISSUE(0); cpa_commit();
    G2_ISSUE(1); cpa_commit();
    G2_ISSUE(2); cpa_commit();

    float cd[4][4][4] = {};
    const int aRow = wm * 64 + (lane & 15);
    const int aK   = (lane >> 4) * 8;
    const int bRow = lane & 15;
    const int bOct = (lane >> 4) * 8;

    for (int kt = 0; kt < KT; kt++) {
        cpa_wait2();
        __syncthreads();
        if (kt + 3 < KT) G2_ISSUE(kt + 3);
        cpa_commit();
        __half* stc = buf + (kt & 3) * G_STAGE_H;
        const uint32_t aAddr = smem_u32(stc + aRow * A_LDA + aK);
        const uint32_t bAddr = smem_u32(stc + A_HALVES + bRow * B_LDB + wn * 32 + bOct);
        uint32_t af[4][4], bd[2][4];
#pragma unroll
        for (int mt = 0; mt < 4; mt++) ldsm4(af[mt], aAddr + mt * 16 * A_LDA * 2);
#pragma unroll
        for (int p = 0; p < 2; p++) ldsm4t(bd[p], bAddr + p * 32);
#pragma unroll
        for (int nt = 0; nt < 4; nt++) {
            const uint32_t* b = &bd[nt >> 1][(nt & 1) * 2];
#pragma unroll
            for (int mt = 0; mt < 4; mt++) mma16(cd[mt][nt], af[mt], b);
        }
    }
#undef G2_ISSUE
#pragma unroll
    for (int mt = 0; mt < 4; mt++) {
#pragma unroll
        for (int h = 0; h < 2; h++) {
            const int lr = wm * 64 + mt * 16 + gid + h * 8;
            const int p = prs[lr];
            if (p >= 0) {
                const float wv = g_topkw[p];
                const int tok = p >> 3;
                float* dst = out + (size_t)tok * HDIM + n0 + wn * 32;
#pragma unroll
                for (int nt = 0; nt < 4; nt++) {
                    atomicAdd(dst + nt * 8 + 2 * tig,     wv * cd[mt][nt][h * 2 + 0]);
                    atomicAdd(dst + nt * 8 + 2 * tig + 1, wv * cd[mt][nt][h * 2 + 1]);
                }
            }
        }
    }
}

/* ---------------- launch: multi-stream fork/join inside the graph ---------------- */
extern "C" void kernel_launch(void* const* d_in, const int* /*in_sizes*/, int /*n_in*/,
                              void* d_out, int /*out_size*/) {
    const float* x   = (const float*)d_in[0];
    const float* gw  = (const float*)d_in[1];
    const float* wgt = (const float*)d_in[2];
    const float* wup = (const float*)d_in[3];
    const float* wdn = (const float*)d_in[4];
    float* out = (float*)d_out;

    /* created once on the (uncaptured) correctness call; reused under capture */
    static cudaStream_t s1 = nullptr, s2 = nullptr;
    static cudaEvent_t evF = nullptr, ev1 = nullptr, ev2 = nullptr;
    static bool inited = false;
    if (!inited) {
        cudaStreamCreateWithFlags(&s1, cudaStreamNonBlocking);
        cudaStreamCreateWithFlags(&s2, cudaStreamNonBlocking);
        cudaEventCreateWithFlags(&evF, cudaEventDisableTiming);
        cudaEventCreateWithFlags(&ev1, cudaEventDisableTiming);
        cudaEventCreateWithFlags(&ev2, cudaEventDisableTiming);
        cudaFuncSetAttribute(k_gemm1, cudaFuncAttributeMaxDynamicSharedMemorySize, G_SMEM);
        cudaFuncSetAttribute(k_gemm2, cudaFuncAttributeMaxDynamicSharedMemorySize, G_SMEM);
        inited = true;
    }

    const size_t nW = (size_t)NEXP * HDIM * IDIM / 8;
    const size_t nX = (size_t)TTOK * HDIM / 8;
    const size_t nA = (size_t)NPAIR * IDIM / 8;
    const unsigned gW = (unsigned)((nW + 255) / 256);

    /* fork side streams off the captured (legacy) stream */
    cudaEventRecord(evF, 0);
    cudaStreamWaitEvent(s1, evF, 0);
    cudaStreamWaitEvent(s2, evF, 0);

    /* s1: gate/up weight conversion (gemm1 dependency) */
    k_cvt<<<gW, 256, 0, s1>>>((const float4*)wgt, 0, nW);
    k_cvt<<<gW, 256, 0, s1>>>((const float4*)wup, 1, nW);
    cudaEventRecord(ev1, s1);

    /* s2: down weight conversion (gemm2 dependency; hides behind gemm1) */
    k_cvt<<<gW, 256, 0, s2>>>((const float4*)wdn, 2, nW);
    cudaEventRecord(ev2, s2);

    /* main stream: routing chain (overlaps the DRAM-bound cvts) */
    k_zero_out<<<TTOK * HDIM / 4 / 256, 256>>>((float4*)out);
    k_zero_counts<<<1, 64>>>();
    k_cvt<<<(unsigned)((nX + 255) / 256), 256>>>((const float4*)x, 3, nX);
    k_router<<<TTOK / 64, 256>>>(x, gw);
    k_topk<<<TTOK / 256, 256>>>();
    k_scan<<<1, 1>>>();

    cudaStreamWaitEvent(0, ev1, 0);   /* join s1 */
    k_gemm1<<<dim3(CAP / 128, IDIM / 128, NEXP * 2), 256, G_SMEM>>>();
    k_silu<<<(unsigned)((nA + 255) / 256), 256>>>();
    cudaStreamWaitEvent(0, ev2, 0);   /* join s2 */
    k_gemm2<<<dim3(CAP / 128, HDIM / 128, NEXP), 256, G_SMEM>>>(out);
}